// round 14
// baseline (speedup 1.0000x reference)
#include <cuda_runtime.h>

#define NBATCH 2048
#define NTOT   6561          // 3^8
#define NQUAD  1640          // full 4-group (144B) quads; group 6560 is the tail
#define GBLK   64
#define TBLK   128           // 64*128 = 8192 threads; 4 threads per batch element
#define NWARPS (GBLK * 4)    // 256 warp-arrivals per barrier epoch
#define ASTRIDE 128          // s64 stride (1KB) -> accumulators hit distinct LTS

#define SCALE_F 1099511627776.0f      // 2^40  (exact in fp32)
#define INV_SF  9.094947017729282e-13f // 2^-40 (exact in fp32)

__device__ long long g_acc[10 * ASTRIDE]; // [k*ASTRIDE]: buckets 0..8, S at k=9
__device__ int g_ctr;        // warp-arrival counter (monotonic, never reset)
__device__ int g_ctr2;       // epoch-reset ticket (monotonic, never reset)

__device__ __forceinline__ float rcpa(float v) {
    float r; asm("rcp.approx.f32 %0, %1;" : "=f"(r) : "f"(v)); return r;
}
__device__ __forceinline__ float lg2a(float v) {
    float r; asm("lg2.approx.f32 %0, %1;" : "=f"(r) : "f"(v)); return r;
}
__device__ __forceinline__ float ex2a(float v) {
    float r; asm("ex2.approx.f32 %0, %1;" : "=f"(r) : "f"(v)); return r;
}
__device__ __forceinline__ int ld_acq(const int* p) {
    int v; asm volatile("ld.acquire.gpu.global.u32 %0, [%1];" : "=r"(v) : "l"(p) : "memory");
    return v;
}
__device__ __forceinline__ void red_s64(long long* p, float v) {
    long long q = (long long)(v * SCALE_F);
    asm volatile("red.relaxed.gpu.global.add.u64 [%0], %1;" :: "l"(p), "l"(q) : "memory");
}

// (1+t), t = ((x-c)/a)^(2b) via log form: t = ex2(b*lg2((x-c)^2) - K),
// K = b*lg2(a^2). Edge cases vs numpy:
//   b==0        -> t=1 (explicit guard; 0**0 == inf**0 == 1)
//   x2==0, b>0  -> lg2=-inf -> t=0   (automatic)
//   a==0,  b>0  -> K=-inf   -> t=inf (automatic; P -> 0)
__device__ __forceinline__ float one_plus_t(float x, float b, float c, float K) {
    float d  = x - c;
    float x2 = d * d;
    float t  = ex2a(fmaf(b, lg2a(x2), -K));
    if (b == 0.0f) t = 1.0f;
    return 1.0f + t;
}

__global__ __launch_bounds__(TBLK)
void anfis_fused(const float* __restrict__ inp,
                 const float* __restrict__ prem,
                 const float* __restrict__ conseq,
                 float* __restrict__ out) {
    __shared__ int sDone;            // spin-exit flag (warp 0 only)

    const int tid  = threadIdx.x;
    const int bi   = blockIdx.x;
    const int w    = tid >> 5, lane = tid & 31;
    const int quarter = lane >> 3;                 // var pair (0..3)
    const int j    = lane & 7;                     // role within 8-lane group
    const int b    = bi * 32 + w * 8 + j;          // batch element

    // ---- Early epoch read: target invariant for any read during this epoch ----
    int ectr = 0;
    if (tid < 4) ectr = __ldcg(&g_ctr);

    // Conseq quads on lanes 24..31 of every warp, warp-interleaved for balance.
    float4 cv[9];
    const int qidx = (lane - 24) * 4 + w;          // 0..31 for lanes 24..31
    const int q    = bi + GBLK * qidx;
    const bool qact = (lane >= 24) && (qidx < 26) && (q < NQUAD);
    if (qact) {
        const float4* p = (const float4*)(conseq + 36 * q);
#pragma unroll
        for (int m = 0; m < 9; m++) cv[m] = __ldg(p + m);
    }

    // Tail group 6560: block 0 / warp 0 / lanes 24..31, folded pre-butterfly.
    float tail_v = 0.0f, tail_8 = 0.0f;
    if (bi == 0 && w == 0 && lane >= 24) {
        tail_v = __ldg(conseq + 36 * NQUAD + (lane - 24));
        if (lane == 24) tail_8 = __ldg(conseq + 36 * NQUAD + 8);
    }

    const int i0 = 2 * quarter;                    // this thread's two vars
    const float x0 = __ldg(inp + i0 * NBATCH + b);
    const float x1 = __ldg(inp + (i0 + 1) * NBATCH + b);

    // 18 premise floats (rows 3*i0 .. 3*i0+5) as 9 float2 loads (8B aligned)
    const float2* pr = (const float2*)(prem + 18 * quarter);
    float pp[18];
#pragma unroll
    for (int m = 0; m < 9; m++) {
        float2 v = __ldg(pr + m);
        pp[2 * m] = v.x; pp[2 * m + 1] = v.y;
    }

    // ---- K constants: lane j<6 of each group computes K_j = b_j*lg2(a_j^2) ----
    float Kv = 0.0f;
    if (j < 6) {
        const float aj = __ldg(prem + 18 * quarter + 3 * j);
        const float bj = __ldg(prem + 18 * quarter + 3 * j + 1);
        Kv = bj * 2.0f * lg2a(fabsf(aj));
    }
    const int gb = lane & 24;
    const float K0 = __shfl_sync(0xffffffffu, Kv, gb + 0);
    const float K1 = __shfl_sync(0xffffffffu, Kv, gb + 1);
    const float K2 = __shfl_sync(0xffffffffu, Kv, gb + 2);
    const float K3 = __shfl_sync(0xffffffffu, Kv, gb + 3);
    const float K4 = __shfl_sync(0xffffffffu, Kv, gb + 4);
    const float K5 = __shfl_sync(0xffffffffu, Kv, gb + 5);

    // ---- Memberships: 2 vars x 3 sets per thread (12 MUFU) ----
    float q0 = one_plus_t(x0, pp[1],  pp[2],  K0) * one_plus_t(x1, pp[10], pp[11], K3);
    float q1 = one_plus_t(x0, pp[4],  pp[5],  K1) * one_plus_t(x1, pp[13], pp[14], K4);
    float q2 = one_plus_t(x0, pp[7],  pp[8],  K2) * one_plus_t(x1, pp[16], pp[17], K5);

    // combine the 4 quarter-lanes (lane bits 3,4)
    q0 *= __shfl_xor_sync(0xffffffffu, q0, 8);
    q1 *= __shfl_xor_sync(0xffffffffu, q1, 8);
    q2 *= __shfl_xor_sync(0xffffffffu, q2, 8);
    q0 *= __shfl_xor_sync(0xffffffffu, q0, 16);
    q1 *= __shfl_xor_sync(0xffffffffu, q1, 16);
    q2 *= __shfl_xor_sync(0xffffffffu, q2, 16);
    const float P0 = rcpa(q0);
    float S = P0 + rcpa(q1) + rcpa(q2);

    // warp S sum over the 8 distinct elements (lane bits 0..2 only)
    S += __shfl_xor_sync(0xffffffffu, S, 1);
    S += __shfl_xor_sync(0xffffffffu, S, 2);
    S += __shfl_xor_sync(0xffffffffu, S, 4);

    // ---- Accumulate conseq quad into Ctot[9] buckets ----
    float acc[9];
#pragma unroll
    for (int v = 0; v < 9; v++) acc[v] = 0.0f;
    if (qact) {
#pragma unroll
        for (int m = 0; m < 9; m++) {
            acc[(4 * m + 0) % 9] += cv[m].x;
            acc[(4 * m + 1) % 9] += cv[m].y;
            acc[(4 * m + 2) % 9] += cv[m].z;
            acc[(4 * m + 3) % 9] += cv[m].w;
        }
    }
    if (bi == 0 && w == 0 && lane >= 24) {         // fold tail group
        acc[lane - 24] += tail_v;
        if (lane == 24) acc[8] += tail_8;
    }
    // butterfly over lanes 24..31 (bits 0..2; inactive lanes hold zeros)
#pragma unroll
    for (int v = 0; v < 9; v++) {
        acc[v] += __shfl_xor_sync(0xffffffffu, acc[v], 1);
        acc[v] += __shfl_xor_sync(0xffffffffu, acc[v], 2);
        acc[v] += __shfl_xor_sync(0xffffffffu, acc[v], 4);
    }

    // ---- Publish: s64 fixed-point reds (deterministic), per-warp release ----
    if (lane >= 24) red_s64(&g_acc[(lane - 24) * ASTRIDE], acc[lane - 24]);
    if (lane == 25) red_s64(&g_acc[8 * ASTRIDE], acc[8]);
    if (lane == 0)  red_s64(&g_acc[9 * ASTRIDE], S);
    if (tid == 4)   sDone = 0;                     // warp 0, pre-syncwarp
    __syncwarp();
    if (lane == 0)
        asm volatile("red.release.gpu.global.add.u32 [%0], %1;"
                     :: "l"(&g_ctr), "r"(1) : "memory");

    // ---- Spin: warp 0 lanes 0..3, staggered, shared exit flag ----
    if (tid < 4) {
        const int target = (ectr / NWARPS + 1) * NWARPS;
        volatile int* vd = &sDone;
        while (true) {
            if (*vd) break;
            if (ld_acq(&g_ctr) >= target) { *vd = 1; break; }
        }
    }
    __syncthreads();

    // ---- Fold: 4 scalar L2 loads per thread, convert from fixed-point ----
    const float C0 = (float)__ldcg(&g_acc[i0 * ASTRIDE]) * INV_SF;
    const float C1 = (float)__ldcg(&g_acc[(i0 + 1) * ASTRIDE]) * INV_SF;
    const float C8 = (float)__ldcg(&g_acc[8 * ASTRIDE]) * INV_SF;
    const float St = (float)__ldcg(&g_acc[9 * ASTRIDE]) * INV_SF;

    // ---- Finalize: dot via butterfly over the 4 quarter-lanes ----
    float d = x0 * C0 + x1 * C1;
    d += __shfl_xor_sync(0xffffffffu, d, 8);
    d += __shfl_xor_sync(0xffffffffu, d, 16);
    if (quarter == 0)
        out[b] = P0 * (d + C8) * rcpa(2187.0f * St);

    // ---- Epoch reset: last-ticket block zeroes accumulators for next launch ----
    __syncthreads();                               // all fold loads in block done
    if (tid == 0) {
        int old;
        asm volatile("atom.release.gpu.global.add.u32 %0, [%1], %2;"
                     : "=r"(old) : "l"(&g_ctr2), "r"(1) : "memory");
        if ((old & (GBLK - 1)) == GBLK - 1) {      // last block of this epoch
#pragma unroll
            for (int k = 0; k < 10; k++) g_acc[k * ASTRIDE] = 0;
        }
    }
}

extern "C" void kernel_launch(void* const* d_in, const int* in_sizes, int n_in,
                              void* d_out, int out_size) {
    const float* inp    = (const float*)d_in[0];   // (8, 2048)
    const float* prem   = (const float*)d_in[1];   // (24, 3)
    const float* conseq = (const float*)d_in[2];   // (59049, 1)
    float* out = (float*)d_out;                    // (2048, 1)

    anfis_fused<<<GBLK, TBLK>>>(inp, prem, conseq, out);
}

// round 15
// speedup vs baseline: 1.0108x; 1.0108x over previous
#include <cuda_runtime.h>

#define NBATCH 2048
#define NTOT   6561          // 3^8
#define NQUAD  1640          // full 4-group (144B) quads; group 6560 is the tail
#define GBLK   64
#define TBLK   128           // 64*128 = 8192 threads; 4 threads per batch element

__device__ float g_Cpart[9][GBLK]; // bucket-major: fold reads contiguous
__device__ float g_Spart[GBLK];
__device__ int   g_ctr;            // monotonic barrier counter (never reset)

__device__ __forceinline__ float rcpa(float v) {
    float r; asm("rcp.approx.f32 %0, %1;" : "=f"(r) : "f"(v)); return r;
}
__device__ __forceinline__ float lg2a(float v) {
    float r; asm("lg2.approx.f32 %0, %1;" : "=f"(r) : "f"(v)); return r;
}
__device__ __forceinline__ float ex2a(float v) {
    float r; asm("ex2.approx.f32 %0, %1;" : "=f"(r) : "f"(v)); return r;
}
__device__ __forceinline__ int ld_acq(const int* p) {
    int v; asm volatile("ld.acquire.gpu.global.u32 %0, [%1];" : "=r"(v) : "l"(p) : "memory");
    return v;
}

// (1+t), t = ((x-c)/a)^(2b) via log form: t = ex2(b*lg2((x-c)^2) - K),
// K = b*lg2(a^2). Edge cases vs numpy:
//   b==0        -> t=1 (explicit guard; 0**0 == inf**0 == 1)
//   x2==0, b>0  -> lg2=-inf -> t=0   (automatic)
//   a==0,  b>0  -> K=-inf   -> t=inf (automatic; P -> 0)
__device__ __forceinline__ float one_plus_t(float x, float b, float c, float K) {
    float d  = x - c;
    float x2 = d * d;
    float t  = ex2a(fmaf(b, lg2a(x2), -K));
    if (b == 0.0f) t = 1.0f;
    return 1.0f + t;
}

__global__ __launch_bounds__(TBLK)
void anfis_fused(const float* __restrict__ inp,
                 const float* __restrict__ prem,
                 const float* __restrict__ conseq,
                 float* __restrict__ out) {
    __shared__ float swC[4][9];      // per-warp conseq partials
    __shared__ float swS[4];         // per-warp S partials
    __shared__ float sF[8][9];       // fold level-1
    __shared__ float sS[8];
    __shared__ float sC[9];
    __shared__ float sInvZ;
    __shared__ int   sDone;          // spin-exit flag (reset every launch)

    const int tid  = threadIdx.x;
    const int bi   = blockIdx.x;
    const int w    = tid >> 5, lane = tid & 31;
    const int quarter = lane >> 3;                 // var pair (0..3)
    const int j    = lane & 7;                     // role within 8-lane group
    const int b    = bi * 32 + w * 8 + j;          // batch element

    // ---- Early epoch read: target = (r/GBLK+1)*GBLK is invariant for any r
    // read during this launch's epoch of the monotonic counter. ----
    int ectr = 0;
    if (tid < 4) ectr = __ldcg(&g_ctr);
    if (tid == 10) sDone = 0;

    // Conseq quads on lanes 24..31 of every warp, warp-interleaved for balance.
    float4 cv[9];
    const int qidx = (lane - 24) * 4 + w;          // 0..31 for lanes 24..31
    const int q    = bi + GBLK * qidx;
    const bool qact = (lane >= 24) && (qidx < 26) && (q < NQUAD);
    if (qact) {
        const float4* p = (const float4*)(conseq + 36 * q);
#pragma unroll
        for (int m = 0; m < 9; m++) cv[m] = __ldg(p + m);
    }

    // Tail group 6560: block 0 / warp 0 / lanes 24..31, folded pre-butterfly.
    float tail_v = 0.0f, tail_8 = 0.0f;
    if (bi == 0 && w == 0 && lane >= 24) {
        tail_v = __ldg(conseq + 36 * NQUAD + (lane - 24));
        if (lane == 24) tail_8 = __ldg(conseq + 36 * NQUAD + 8);
    }

    const int i0 = 2 * quarter;                    // this thread's two vars
    const float x0 = __ldg(inp + i0 * NBATCH + b);
    const float x1 = __ldg(inp + (i0 + 1) * NBATCH + b);

    // 18 premise floats (rows 3*i0 .. 3*i0+5) as 9 float2 loads (8B aligned)
    const float2* pr = (const float2*)(prem + 18 * quarter);
    float pp[18];
#pragma unroll
    for (int m = 0; m < 9; m++) {
        float2 v = __ldg(pr + m);
        pp[2 * m] = v.x; pp[2 * m + 1] = v.y;
    }

    // ---- K constants: lane j<6 of each group computes K_j = b_j*lg2(a_j^2) ----
    float Kv = 0.0f;
    if (j < 6) {
        const float aj = __ldg(prem + 18 * quarter + 3 * j);
        const float bj = __ldg(prem + 18 * quarter + 3 * j + 1);
        Kv = bj * 2.0f * lg2a(fabsf(aj));
    }
    const int gb = lane & 24;
    const float K0 = __shfl_sync(0xffffffffu, Kv, gb + 0);
    const float K1 = __shfl_sync(0xffffffffu, Kv, gb + 1);
    const float K2 = __shfl_sync(0xffffffffu, Kv, gb + 2);
    const float K3 = __shfl_sync(0xffffffffu, Kv, gb + 3);
    const float K4 = __shfl_sync(0xffffffffu, Kv, gb + 4);
    const float K5 = __shfl_sync(0xffffffffu, Kv, gb + 5);

    // ---- Memberships: 2 vars x 3 sets per thread (12 MUFU) ----
    float q0 = one_plus_t(x0, pp[1],  pp[2],  K0) * one_plus_t(x1, pp[10], pp[11], K3);
    float q1 = one_plus_t(x0, pp[4],  pp[5],  K1) * one_plus_t(x1, pp[13], pp[14], K4);
    float q2 = one_plus_t(x0, pp[7],  pp[8],  K2) * one_plus_t(x1, pp[16], pp[17], K5);

    // combine the 4 quarter-lanes (lane bits 3,4)
    q0 *= __shfl_xor_sync(0xffffffffu, q0, 8);
    q1 *= __shfl_xor_sync(0xffffffffu, q1, 8);
    q2 *= __shfl_xor_sync(0xffffffffu, q2, 8);
    q0 *= __shfl_xor_sync(0xffffffffu, q0, 16);
    q1 *= __shfl_xor_sync(0xffffffffu, q1, 16);
    q2 *= __shfl_xor_sync(0xffffffffu, q2, 16);
    const float P0 = rcpa(q0);
    float S = P0 + rcpa(q1) + rcpa(q2);

    // warp S sum over the 8 distinct elements (lane bits 0..2 only)
    S += __shfl_xor_sync(0xffffffffu, S, 1);
    S += __shfl_xor_sync(0xffffffffu, S, 2);
    S += __shfl_xor_sync(0xffffffffu, S, 4);

    // ---- Accumulate conseq quad into Ctot[9] buckets ----
    float acc[9];
#pragma unroll
    for (int v = 0; v < 9; v++) acc[v] = 0.0f;
    if (qact) {
#pragma unroll
        for (int m = 0; m < 9; m++) {
            acc[(4 * m + 0) % 9] += cv[m].x;
            acc[(4 * m + 1) % 9] += cv[m].y;
            acc[(4 * m + 2) % 9] += cv[m].z;
            acc[(4 * m + 3) % 9] += cv[m].w;
        }
    }
    if (bi == 0 && w == 0 && lane >= 24) {         // fold tail group
        acc[lane - 24] += tail_v;
        if (lane == 24) acc[8] += tail_8;
    }
    // butterfly over lanes 24..31 (bits 0..2; inactive lanes hold zeros)
#pragma unroll
    for (int v = 0; v < 9; v++) {
        acc[v] += __shfl_xor_sync(0xffffffffu, acc[v], 1);
        acc[v] += __shfl_xor_sync(0xffffffffu, acc[v], 2);
        acc[v] += __shfl_xor_sync(0xffffffffu, acc[v], 4);
    }
    if (lane >= 24) swC[w][lane - 24] = acc[lane - 24];
    if (lane == 24) swC[w][8] = acc[8];
    if (lane == 0)  swS[w] = S;
    __syncthreads();

    // ---- Parallel publish of this block's partials (bucket-major) ----
    if (tid < 9)
        g_Cpart[tid][bi] = swC[0][tid] + swC[1][tid] + swC[2][tid] + swC[3][tid];
    if (tid == 9)
        g_Spart[bi] = swS[0] + swS[1] + swS[2] + swS[3];
    __syncthreads();

    // ---- Grid barrier: release-red, then 4 staggered spinners ----
    if (tid == 0)
        asm volatile("red.release.gpu.global.add.u32 [%0], %1;"
                     :: "l"(&g_ctr), "r"(1) : "memory");
    if (tid < 4) {
        const int target = (ectr / GBLK + 1) * GBLK;
        volatile int* vd = &sDone;
        while (true) {
            if (*vd) break;
            if (ld_acq(&g_ctr) >= target) { *vd = 1; break; }
        }
    }
    __syncthreads();

    // ---- Two-level fold of 64 partials (vectorized L2 reads) ----
    if (tid < 72) {                                // 9 buckets x 8 parts
        const int v = tid >> 3, pt = tid & 7;
        const float4* p = (const float4*)&g_Cpart[v][pt * 8];
        float4 u0 = __ldcg(p), u1 = __ldcg(p + 1);
        sF[pt][v] = ((u0.x + u0.y) + (u0.z + u0.w))
                  + ((u1.x + u1.y) + (u1.z + u1.w));
    }
    if (tid >= 72 && tid < 80) {                   // 8 parts of S
        const int pt = tid - 72;
        const float4* p = (const float4*)&g_Spart[pt * 8];
        float4 u0 = __ldcg(p), u1 = __ldcg(p + 1);
        sS[pt] = ((u0.x + u0.y) + (u0.z + u0.w))
               + ((u1.x + u1.y) + (u1.z + u1.w));
    }
    __syncthreads();
    if (tid < 9) {
        float s = 0.0f;
#pragma unroll
        for (int p = 0; p < 8; p++) s += sF[p][tid];
        sC[tid] = s;
    }
    if (tid == 9) {
        float s = 0.0f;
#pragma unroll
        for (int p = 0; p < 8; p++) s += sS[p];
        sInvZ = 1.0f / (2187.0f * s);              // Z = 2187 * sum_b (P0+P1+P2)
    }
    __syncthreads();

    // ---- Finalize: dot via butterfly over the 4 quarter-lanes ----
    float d = x0 * sC[i0] + x1 * sC[i0 + 1];
    d += __shfl_xor_sync(0xffffffffu, d, 8);
    d += __shfl_xor_sync(0xffffffffu, d, 16);
    if (quarter == 0)
        out[b] = P0 * (d + sC[8]) * sInvZ;
}

extern "C" void kernel_launch(void* const* d_in, const int* in_sizes, int n_in,
                              void* d_out, int out_size) {
    const float* inp    = (const float*)d_in[0];   // (8, 2048)
    const float* prem   = (const float*)d_in[1];   // (24, 3)
    const float* conseq = (const float*)d_in[2];   // (59049, 1)
    float* out = (float*)d_out;                    // (2048, 1)

    anfis_fused<<<GBLK, TBLK>>>(inp, prem, conseq, out);
}

// round 16
// speedup vs baseline: 1.0564x; 1.0451x over previous
#include <cuda_runtime.h>

#define NBATCH 2048
#define NTOT   6561          // 3^8
#define NQUAD  1640          // full 4-group (144B) quads; group 6560 is the tail
#define GBLK   64            // k1 blocks
#define TBLK   128
#define GBLK2  16            // k2 blocks (16*128 = 2048 = one thread per element)
#define ASTRIDE 128          // s64 stride (1KB) -> accumulators hit distinct LTS

#define SCALE_F 1099511627776.0f       // 2^40  (exact in fp32)
#define INV_SF  9.094947017729282e-13f // 2^-40 (exact in fp32)

__device__ long long g_acc[10 * ASTRIDE]; // [k*ASTRIDE]: C buckets 0..8, S at k=9
__device__ int g_ctr2;                    // epoch-reset ticket (monotonic)

__device__ __forceinline__ float rcpa(float v) {
    float r; asm("rcp.approx.f32 %0, %1;" : "=f"(r) : "f"(v)); return r;
}
__device__ __forceinline__ float lg2a(float v) {
    float r; asm("lg2.approx.f32 %0, %1;" : "=f"(r) : "f"(v)); return r;
}
__device__ __forceinline__ float ex2a(float v) {
    float r; asm("ex2.approx.f32 %0, %1;" : "=f"(r) : "f"(v)); return r;
}
__device__ __forceinline__ void red_s64(long long* p, float v) {
    long long q = (long long)(v * SCALE_F);
    asm volatile("red.relaxed.gpu.global.add.u64 [%0], %1;" :: "l"(p), "l"(q) : "memory");
}

// K-form: (1+t), t = ex2(b*lg2((x-c)^2) - K), K = b*lg2(a^2). numpy edge cases:
//   b==0 -> t=1 (guard); x2==0,b>0 -> t=0 (auto); a==0,b>0 -> t=inf (auto, P->0)
__device__ __forceinline__ float one_plus_t_K(float x, float b, float c, float K) {
    float d  = x - c;
    float x2 = d * d;
    float t  = ex2a(fmaf(b, lg2a(x2), -K));
    if (b == 0.0f) t = 1.0f;
    return 1.0f + t;
}
// Direct form (k2): t = ((x-c)*rcp(a))^2 ^ b, same edge cases explicit.
__device__ __forceinline__ float one_plus_t_D(float x, float a, float b, float c) {
    float u  = (x - c) * rcpa(a);
    float x2 = u * u;
    float t;
    if (b == 0.0f)       t = 1.0f;
    else if (x2 == 0.0f) t = 0.0f;
    else                 t = ex2a(b * lg2a(x2));
    return 1.0f + t;
}

// ================= k1: reduce (C buckets + global S) =================
__global__ __launch_bounds__(TBLK)
void anfis_reduce(const float* __restrict__ inp,
                  const float* __restrict__ prem,
                  const float* __restrict__ conseq) {
    // Allow the dependent kernel to launch immediately (PDL overlap).
    asm volatile("griddepcontrol.launch_dependents;" ::: "memory");

    __shared__ float swC[4][9];
    __shared__ float swS[4];

    const int tid  = threadIdx.x;
    const int bi   = blockIdx.x;
    const int w    = tid >> 5, lane = tid & 31;
    const int quarter = lane >> 3;                 // var pair (0..3)
    const int j    = lane & 7;
    const int b    = bi * 32 + w * 8 + j;          // batch element

    // Conseq quads on lanes 24..31 of every warp, warp-interleaved for balance.
    float4 cv[9];
    const int qidx = (lane - 24) * 4 + w;          // 0..31 for lanes 24..31
    const int q    = bi + GBLK * qidx;
    const bool qact = (lane >= 24) && (qidx < 26) && (q < NQUAD);
    if (qact) {
        const float4* p = (const float4*)(conseq + 36 * q);
#pragma unroll
        for (int m = 0; m < 9; m++) cv[m] = __ldg(p + m);
    }

    // Tail group 6560: block 0 / warp 0 / lanes 24..31, folded pre-butterfly.
    float tail_v = 0.0f, tail_8 = 0.0f;
    if (bi == 0 && w == 0 && lane >= 24) {
        tail_v = __ldg(conseq + 36 * NQUAD + (lane - 24));
        if (lane == 24) tail_8 = __ldg(conseq + 36 * NQUAD + 8);
    }

    const int i0 = 2 * quarter;
    const float x0 = __ldg(inp + i0 * NBATCH + b);
    const float x1 = __ldg(inp + (i0 + 1) * NBATCH + b);

    const float2* pr = (const float2*)(prem + 18 * quarter);
    float pp[18];
#pragma unroll
    for (int m = 0; m < 9; m++) {
        float2 v = __ldg(pr + m);
        pp[2 * m] = v.x; pp[2 * m + 1] = v.y;
    }

    // K constants: lane j<6 of each group computes K_j = b_j*lg2(a_j^2)
    float Kv = 0.0f;
    if (j < 6) {
        const float aj = __ldg(prem + 18 * quarter + 3 * j);
        const float bj = __ldg(prem + 18 * quarter + 3 * j + 1);
        Kv = bj * 2.0f * lg2a(fabsf(aj));
    }
    const int gb = lane & 24;
    const float K0 = __shfl_sync(0xffffffffu, Kv, gb + 0);
    const float K1 = __shfl_sync(0xffffffffu, Kv, gb + 1);
    const float K2 = __shfl_sync(0xffffffffu, Kv, gb + 2);
    const float K3 = __shfl_sync(0xffffffffu, Kv, gb + 3);
    const float K4 = __shfl_sync(0xffffffffu, Kv, gb + 4);
    const float K5 = __shfl_sync(0xffffffffu, Kv, gb + 5);

    float q0 = one_plus_t_K(x0, pp[1],  pp[2],  K0) * one_plus_t_K(x1, pp[10], pp[11], K3);
    float q1 = one_plus_t_K(x0, pp[4],  pp[5],  K1) * one_plus_t_K(x1, pp[13], pp[14], K4);
    float q2 = one_plus_t_K(x0, pp[7],  pp[8],  K2) * one_plus_t_K(x1, pp[16], pp[17], K5);

    q0 *= __shfl_xor_sync(0xffffffffu, q0, 8);
    q1 *= __shfl_xor_sync(0xffffffffu, q1, 8);
    q2 *= __shfl_xor_sync(0xffffffffu, q2, 8);
    q0 *= __shfl_xor_sync(0xffffffffu, q0, 16);
    q1 *= __shfl_xor_sync(0xffffffffu, q1, 16);
    q2 *= __shfl_xor_sync(0xffffffffu, q2, 16);
    float S = rcpa(q0) + rcpa(q1) + rcpa(q2);

    // warp S sum over the 8 distinct elements (lane bits 0..2 only)
    S += __shfl_xor_sync(0xffffffffu, S, 1);
    S += __shfl_xor_sync(0xffffffffu, S, 2);
    S += __shfl_xor_sync(0xffffffffu, S, 4);

    // Conseq buckets
    float acc[9];
#pragma unroll
    for (int v = 0; v < 9; v++) acc[v] = 0.0f;
    if (qact) {
#pragma unroll
        for (int m = 0; m < 9; m++) {
            acc[(4 * m + 0) % 9] += cv[m].x;
            acc[(4 * m + 1) % 9] += cv[m].y;
            acc[(4 * m + 2) % 9] += cv[m].z;
            acc[(4 * m + 3) % 9] += cv[m].w;
        }
    }
    if (bi == 0 && w == 0 && lane >= 24) {
        acc[lane - 24] += tail_v;
        if (lane == 24) acc[8] += tail_8;
    }
#pragma unroll
    for (int v = 0; v < 9; v++) {
        acc[v] += __shfl_xor_sync(0xffffffffu, acc[v], 1);
        acc[v] += __shfl_xor_sync(0xffffffffu, acc[v], 2);
        acc[v] += __shfl_xor_sync(0xffffffffu, acc[v], 4);
    }
    if (lane >= 24) swC[w][lane - 24] = acc[lane - 24];
    if (lane == 24) swC[w][8] = acc[8];
    if (lane == 0)  swS[w] = S;
    __syncthreads();

    // Publish: deterministic s64 fixed-point reds (one set per block).
    if (tid < 9)
        red_s64(&g_acc[tid * ASTRIDE],
                ((swC[0][tid] + swC[1][tid]) + (swC[2][tid] + swC[3][tid])));
    if (tid == 9)
        red_s64(&g_acc[9 * ASTRIDE],
                ((swS[0] + swS[1]) + (swS[2] + swS[3])));
}

// ================= k2: finalize (PDL-overlapped) =================
__global__ __launch_bounds__(TBLK)
void anfis_final(const float* __restrict__ inp,
                 const float* __restrict__ prem,
                 float* __restrict__ out) {
    const int tid = threadIdx.x;
    const int b   = blockIdx.x * TBLK + tid;       // one element per thread

    // --- Pre-sync work: fully overlapped with k1 ---
    float x[8];
#pragma unroll
    for (int i = 0; i < 8; i++) x[i] = __ldg(inp + i * NBATCH + b);

    float q0 = 1.0f;
#pragma unroll
    for (int i = 0; i < 8; i++) {
        const float* r = prem + 9 * i;             // set-0 row of variable i
        q0 *= one_plus_t_D(x[i], __ldg(r), __ldg(r + 1), __ldg(r + 2));
    }
    const float P0 = rcpa(q0);

    // --- Wait for k1 completion (HW grid dependency, memory flushed) ---
    asm volatile("griddepcontrol.wait;" ::: "memory");

    float C[9];
#pragma unroll
    for (int v = 0; v < 9; v++)
        C[v] = (float)__ldcg(&g_acc[v * ASTRIDE]) * INV_SF;
    const float St = (float)__ldcg(&g_acc[9 * ASTRIDE]) * INV_SF;

    float dot = C[8];                              // bias
#pragma unroll
    for (int i = 0; i < 8; i++) dot = fmaf(x[i], C[i], dot);
    out[b] = P0 * dot * rcpa(2187.0f * St);        // Z = 2187 * sum_b(P0+P1+P2)

    // --- Epoch reset: last-ticket block zeroes accumulators for next launch.
    // release-atom orders this block's scalar reads before the ticket; the
    // last block therefore zeroes only after every block has read. Kernel
    // boundary orders the zeroing before the next launch's k1 reds.
    __syncthreads();
    if (tid == 0) {
        int old;
        asm volatile("atom.release.gpu.global.add.u32 %0, [%1], %2;"
                     : "=r"(old) : "l"(&g_ctr2), "r"(1) : "memory");
        if ((old & (GBLK2 - 1)) == GBLK2 - 1) {
#pragma unroll
            for (int k = 0; k < 10; k++) g_acc[k * ASTRIDE] = 0;
        }
    }
}

extern "C" void kernel_launch(void* const* d_in, const int* in_sizes, int n_in,
                              void* d_out, int out_size) {
    const float* inp    = (const float*)d_in[0];   // (8, 2048)
    const float* prem   = (const float*)d_in[1];   // (24, 3)
    const float* conseq = (const float*)d_in[2];   // (59049, 1)
    float* out = (float*)d_out;                    // (2048, 1)

    anfis_reduce<<<GBLK, TBLK>>>(inp, prem, conseq);

    cudaLaunchConfig_t cfg = {};
    cfg.gridDim  = dim3(GBLK2, 1, 1);
    cfg.blockDim = dim3(TBLK, 1, 1);
    cfg.dynamicSmemBytes = 0;
    cfg.stream = 0;                                // same (default) stream
    cudaLaunchAttribute attr[1];
    attr[0].id = cudaLaunchAttributeProgrammaticStreamSerialization;
    attr[0].val.programmaticStreamSerializationAllowed = 1;
    cfg.attrs = attr;
    cfg.numAttrs = 1;
    cudaLaunchKernelEx(&cfg, anfis_final, inp, prem, out);
}